// round 2
// baseline (speedup 1.0000x reference)
#include <cuda_runtime.h>
#include <cuda_bf16.h>
#include <cstdint>

// Problem constants (fixed by the reference)
constexpr int B_   = 32;
constexpr int C_   = 3;
constexpr int H_   = 512;
constexpr int W_   = 512;
constexpr int OH_  = 128;
constexpr int OW_  = 64;
constexpr int NNZ_ = 98304;

constexpr int HW_   = H_ * W_;          // 262144
constexpr int CHW_  = C_ * HW_;         // 786432  (per-sample x stride)
constexpr int OHW_  = OH_ * OW_;        // 8192
constexpr int COHW_ = C_ * OHW_;        // 24576   (per-sample out stride)
constexpr int RES_  = B_ * COHW_;       // 786432  (result element count)

constexpr int TPB   = 256;
constexpr int EPT   = 8;                              // entries per thread
constexpr int GRIDX = NNZ_ / (TPB * EPT);             // 48

__global__ void __launch_bounds__(TPB)
tti_fused_kernel(const float* __restrict__ x,
                 const int*   __restrict__ rows,
                 const int*   __restrict__ cols,
                 const float* __restrict__ vals,
                 const float* __restrict__ mask,
                 float*       __restrict__ out,
                 int mask_elems)
{
    const int b = blockIdx.y;

    if (b == B_) {
        // ---- mask pass-through plane: copy mask -> out[RES_ ...] ----
        const float4* __restrict__ m4 = reinterpret_cast<const float4*>(mask);
        float4* __restrict__       o4 = reinterpret_cast<float4*>(out + RES_);
        const int total4 = mask_elems >> 2;
        const int stride = GRIDX * TPB;
        for (int i = blockIdx.x * TPB + threadIdx.x; i < total4; i += stride)
            o4[i] = __ldcs(m4 + i);
        return;
    }

    // ---- scatter plane ----
    const int  k    = (blockIdx.x * TPB + threadIdx.x) * EPT;
    const long base = (long)b * NNZ_ + k;

    // Stream indices/values with evict-first so they don't evict texture
    // sectors from L2 (the duplicate-gather hits live there).
    const int4   rA = __ldcs(reinterpret_cast<const int4*>(rows + base));
    const int4   rB = __ldcs(reinterpret_cast<const int4*>(rows + base + 4));
    const int4   cA = __ldcs(reinterpret_cast<const int4*>(cols + base));
    const int4   cB = __ldcs(reinterpret_cast<const int4*>(cols + base + 4));
    const float4 vA = __ldcs(reinterpret_cast<const float4*>(vals + base));
    const float4 vB = __ldcs(reinterpret_cast<const float4*>(vals + base + 4));

    const float* __restrict__ xb = x + (long)b * CHW_;
    float*       __restrict__ ob = out + (long)b * COHW_;

    const int   cc[EPT] = {cA.x, cA.y, cA.z, cA.w, cB.x, cB.y, cB.z, cB.w};
    const int   rr[EPT] = {rA.x, rA.y, rA.z, rA.w, rB.x, rB.y, rB.z, rB.w};
    const float vv[EPT] = {vA.x, vA.y, vA.z, vA.w, vB.x, vB.y, vB.z, vB.w};

    // Issue all 8 gathers before any atomic: MLP=8 per thread hides the
    // ~577-cycle DRAM gather latency.
    float g[EPT];
#pragma unroll
    for (int i = 0; i < EPT; ++i) {
        const int col = cc[i];
        const int hw  = col / 3;            // spatial index (h*W + w)
        const int ch  = col - 3 * hw;       // channel
        g[i] = __ldg(xb + ch * HW_ + hw);
    }

    // Scatter with global reductions (REDG); avg 4 duplicates per address,
    // spread over 786K addresses -> negligible LTS serialization.
#pragma unroll
    for (int i = 0; i < EPT; ++i) {
        const int row = rr[i];
        const int p   = row / 3;            // oh*OW + ow
        const int rc  = row - 3 * p;        // channel
        atomicAdd(ob + rc * OHW_ + p, vv[i] * g[i]);
    }
}

extern "C" void kernel_launch(void* const* d_in, const int* in_sizes, int n_in,
                              void* d_out, int out_size)
{
    const float* x    = (const float*)d_in[0];
    const int*   rows = (const int*)  d_in[1];
    const int*   cols = (const int*)  d_in[2];
    const float* vals = (const float*)d_in[3];
    const float* mask = (const float*)d_in[4];
    float* out = (float*)d_out;

    // Zero the result region (d_out is poisoned to 0xAA before timing).
    // Separate launch: guarantees ordering before the scatter atomics.
    cudaMemsetAsync(out, 0, (size_t)RES_ * sizeof(float), 0);

    const int mask_elems = out_size - RES_;   // = 786432
    dim3 grid(GRIDX, B_ + 1);                 // y==B_ plane copies the mask
    tti_fused_kernel<<<grid, TPB>>>(x, rows, cols, vals, mask, out, mask_elems);
}

// round 3
// speedup vs baseline: 1.0864x; 1.0864x over previous
#include <cuda_runtime.h>
#include <cuda_bf16.h>
#include <cstdint>

// Problem constants (fixed by the reference)
constexpr int B_   = 32;
constexpr int C_   = 3;
constexpr int H_   = 512;
constexpr int W_   = 512;
constexpr int OH_  = 128;
constexpr int OW_  = 64;
constexpr int NNZ_ = 98304;

constexpr int HW_   = H_ * W_;          // 262144
constexpr int CHW_  = C_ * HW_;         // 786432  (per-sample x stride)
constexpr int OHW_  = OH_ * OW_;        // 8192
constexpr int COHW_ = C_ * OHW_;        // 24576   (per-sample out stride)
constexpr int RES_  = B_ * COHW_;       // 786432  (result element count)

constexpr int TPB   = 256;
constexpr int EPT   = 4;                              // entries per thread
constexpr int GRIDX = NNZ_ / (TPB * EPT);             // 96

__global__ void __launch_bounds__(TPB)
tti_fused_kernel(const float* __restrict__ x,
                 const int*   __restrict__ rows,
                 const int*   __restrict__ cols,
                 const float* __restrict__ vals,
                 const float* __restrict__ mask,
                 float*       __restrict__ out,
                 int mask_elems)
{
    const int b = blockIdx.y;

    if (b == B_) {
        // ---- mask pass-through plane (independent of the scatter work) ----
        const float4* __restrict__ m4 = reinterpret_cast<const float4*>(mask);
        float4* __restrict__       o4 = reinterpret_cast<float4*>(out + RES_);
        const int total4 = mask_elems >> 2;
        const int stride = GRIDX * TPB;
        for (int i = blockIdx.x * TPB + threadIdx.x; i < total4; i += stride)
            o4[i] = m4[i];
        return;
    }

    // ---- scatter plane (R1 shape: EPT=4, regs ~24, occ ~81%) ----
    const int  k    = (blockIdx.x * TPB + threadIdx.x) * EPT;
    const long base = (long)b * NNZ_ + k;

    const int4   r4 = *reinterpret_cast<const int4*>(rows + base);
    const int4   c4 = *reinterpret_cast<const int4*>(cols + base);
    const float4 v4 = *reinterpret_cast<const float4*>(vals + base);

    const float* __restrict__ xb = x + (long)b * CHW_;
    float*       __restrict__ ob = out + (long)b * COHW_;

    const int   cc[EPT] = {c4.x, c4.y, c4.z, c4.w};
    const int   rr[EPT] = {r4.x, r4.y, r4.z, r4.w};
    const float vv[EPT] = {v4.x, v4.y, v4.z, v4.w};

    // Issue all gathers before any atomic (per-thread MLP=4; chip-level MLP
    // comes from ~52 resident warps/SM).
    float g[EPT];
#pragma unroll
    for (int i = 0; i < EPT; ++i) {
        const int col = cc[i];
        const int hw  = col / 3;            // spatial index (h*W + w)
        const int ch  = col - 3 * hw;       // channel
        g[i] = __ldg(xb + ch * HW_ + hw);
    }

    // REDG scatter: avg 4 duplicates per address over 786K addresses.
#pragma unroll
    for (int i = 0; i < EPT; ++i) {
        const int row = rr[i];
        const int p   = row / 3;            // oh*OW + ow
        const int rc  = row - 3 * p;        // channel
        atomicAdd(ob + rc * OHW_ + p, vv[i] * g[i]);
    }
}

extern "C" void kernel_launch(void* const* d_in, const int* in_sizes, int n_in,
                              void* d_out, int out_size)
{
    const float* x    = (const float*)d_in[0];
    const int*   rows = (const int*)  d_in[1];
    const int*   cols = (const int*)  d_in[2];
    const float* vals = (const float*)d_in[3];
    const float* mask = (const float*)d_in[4];
    float* out = (float*)d_out;

    // Node 1: zero the result region (atomics accumulate; out is poisoned).
    cudaMemsetAsync(out, 0, (size_t)RES_ * sizeof(float), 0);

    // Node 2: fused scatter + mask copy.
    const int mask_elems = out_size - RES_;   // = 786432
    dim3 grid(GRIDX, B_ + 1);
    tti_fused_kernel<<<grid, TPB>>>(x, rows, cols, vals, mask, out, mask_elems);
}